// round 7
// baseline (speedup 1.0000x reference)
#include <cuda_runtime.h>
#include <cuda_fp16.h>
#include <stdint.h>

#define NB 8
#define BF 64
#define BN 2048
#define NPAIR 136             // upper-triangle 16x16 tile pairs

// smem layout (dynamic), 66.6 KB/CTA -> 3 CTAs/SM:
//   [0,16K)    A tile   [16K,32K)  B tile
//   [32K,64K)  per-warp transpose staging, 8 x 4KB
//   [64K,+1K)  sqI[128] | sqJ[128]
//   [+1K,+4B)  scale
#define SMEM_STAGE 32768
#define SMEM_SQ    65536
#define SMEM_TOTAL (65536 + 1024 + 16)

// Scratch
__device__ __half g_emb_t[NB * BN * BF];   // transposed: [b][n][f], f contiguous (2 MB)
__device__ float  g_sqn[NB * BN];
__device__ float  g_part_sum[256];
__device__ float  g_part_sq[256];

// ---------------- Pass 1: convert f32->f16 transposed + sqn + std partial sums ----------------
__global__ void convert_reduce_kernel(const float* __restrict__ emb) {
    int b   = blockIdx.y;
    int tid = threadIdx.x;
    int fq  = tid & 3;
    int nl  = tid >> 2;
    int n   = blockIdx.x * 64 + nl;

    const float* e = emb + (size_t)b * BF * BN + (size_t)(fq * 16) * BN + n;

    float s = 0.f, s2 = 0.f, sq = 0.f;
    __half2 hv[8];
#pragma unroll
    for (int i = 0; i < 16; i += 2) {
        float v0 = e[(size_t)i * BN];
        float v1 = e[(size_t)(i + 1) * BN];
        s  += v0 + v1;
        s2 += v0 * v0 + v1 * v1;
        __half h0 = __float2half(v0), h1 = __float2half(v1);
        float w0 = __half2float(h0), w1 = __half2float(h1);
        sq += w0 * w0 + w1 * w1;
        hv[i >> 1] = __halves2half2(h0, h1);
    }
    sq += __shfl_xor_sync(0xffffffffu, sq, 1);
    sq += __shfl_xor_sync(0xffffffffu, sq, 2);
    if (fq == 0) g_sqn[b * BN + n] = sq;

    uint4* dst = (uint4*)(g_emb_t + ((size_t)b * BN + n) * BF + fq * 16);
    const uint4* src = (const uint4*)hv;
    dst[0] = src[0];
    dst[1] = src[1];

    __shared__ float sh[256], sh2[256];
    sh[tid] = s; sh2[tid] = s2;
    __syncthreads();
    for (int o = 128; o > 0; o >>= 1) {
        if (tid < o) { sh[tid] += sh[tid + o]; sh2[tid] += sh2[tid + o]; }
        __syncthreads();
    }
    if (tid == 0) {
        int bi = b * 32 + blockIdx.x;
        g_part_sum[bi] = sh[0];
        g_part_sq[bi]  = sh2[0];
    }
}

// XOR swizzle for 128B rows (tile buffers)
__device__ __forceinline__ uint32_t sw128(uint32_t off) {
    return off ^ (((off >> 7) & 7u) << 4);
}

// ---------------- Pass 2: upper-triangle Gram GEMM + exp + mirrored store, occ=3 ----------------
__global__ __launch_bounds__(256, 3) void gemm_kernel(float* __restrict__ out) {
    extern __shared__ __align__(16) char smem[];
    float* sSq     = (float*)(smem + SMEM_SQ);
    float* s_scale = (float*)(smem + SMEM_SQ + 1024);

    int tid = threadIdx.x;
    uint32_t smemBase = (uint32_t)__cvta_generic_to_shared(smem);

    // decode tile pair (ti <= tj)
    int b = blockIdx.y;
    int t = blockIdx.x;
    int ti = (int)(16.5f - sqrtf(272.25f - 2.0f * (float)t));
    if (ti > 0 && 16 * ti - (ti * (ti - 1)) / 2 > t) --ti;
    while (16 * (ti + 1) - ((ti + 1) * ti) / 2 <= t) ++ti;
    int tj = ti + (t - (16 * ti - (ti * (ti - 1)) / 2));
    int i0 = ti * 128;
    int j0 = tj * 128;

    // tile + sqn loads
    {
        const char* EA = (const char*)(g_emb_t + ((size_t)b * BN + i0) * BF);
        const char* EB = (const char*)(g_emb_t + ((size_t)b * BN + j0) * BF);
#pragma unroll
        for (int tt = 0; tt < 4; ++tt) {
            uint32_t off = (uint32_t)(tid + tt * 256) * 16u;
            uint32_t sw  = sw128(off);
            asm volatile("cp.async.ca.shared.global [%0], [%1], 16;" :: "r"(smemBase + sw),          "l"(EA + off));
            asm volatile("cp.async.ca.shared.global [%0], [%1], 16;" :: "r"(smemBase + 16384u + sw), "l"(EB + off));
        }
        if (tid < 32) {
            const char* gI = (const char*)(g_sqn + b * BN + i0) + tid * 16;
            const char* gJ = (const char*)(g_sqn + b * BN + j0) + tid * 16;
            asm volatile("cp.async.ca.shared.global [%0], [%1], 16;" :: "r"(smemBase + SMEM_SQ + tid * 16u),        "l"(gI));
            asm volatile("cp.async.ca.shared.global [%0], [%1], 16;" :: "r"(smemBase + SMEM_SQ + 512u + tid * 16u), "l"(gJ));
        }
        asm volatile("cp.async.commit_group;");
    }

    // scale reduction (overlapped with loads)
    if (tid < 32) {
        float ps = 0.f, pq = 0.f;
#pragma unroll
        for (int i = 0; i < 8; ++i) {
            ps += g_part_sum[tid + 32 * i];
            pq += g_part_sq[tid + 32 * i];
        }
#pragma unroll
        for (int o = 16; o > 0; o >>= 1) {
            ps += __shfl_xor_sync(0xffffffffu, ps, o);
            pq += __shfl_xor_sync(0xffffffffu, pq, o);
        }
        if (tid == 0) {
            double nn  = (double)(NB * BF * BN);
            double var = ((double)pq - (double)ps * (double)ps / nn) / (nn - 1.0);
            *s_scale = (float)(1.4426950408889634 / (var * (double)BF * 2.0));
        }
    }

    asm volatile("cp.async.wait_group 0;");
    __syncthreads();

    int warp = tid >> 5, lane = tid & 31;
    int wm = (warp >> 2) * 64;    // warp rows: 0 or 64
    int wn = (warp & 3) * 32;     // warp cols: 0..96
    float l2s = *s_scale;
    float k2  = 2.f * l2s;
    float* wstg = (float*)(smem + SMEM_STAGE + warp * 4096);
    uint32_t aBase = smemBase;
    uint32_t bBase = smemBase + 16384u;
    const float* sSqI = sSq;
    const float* sSqJ = sSq + 128;

    // two N-halves of 16 cols each -> 32 live accumulators
#pragma unroll
    for (int h = 0; h < 2; ++h) {
        float c[4][2][4];
#pragma unroll
        for (int mt = 0; mt < 4; ++mt)
#pragma unroll
            for (int nt = 0; nt < 2; ++nt)
#pragma unroll
                for (int q = 0; q < 4; ++q) c[mt][nt][q] = 0.f;

#pragma unroll
        for (int kk = 0; kk < 4; ++kk) {
            int k0 = kk * 16;

            uint32_t bfr[2][2];
            {
                int nrow = wn + h * 16 + (lane & 7) + ((lane >> 4) << 3);
                int col  = k0 + (((lane >> 3) & 1) << 3);
                uint32_t addr = bBase + sw128((uint32_t)(nrow * 128 + col * 2));
                asm volatile("ldmatrix.sync.aligned.m8n8.x4.shared.b16 {%0,%1,%2,%3}, [%4];"
                             : "=r"(bfr[0][0]), "=r"(bfr[0][1]), "=r"(bfr[1][0]), "=r"(bfr[1][1])
                             : "r"(addr));
            }

#pragma unroll
            for (int mt = 0; mt < 4; ++mt) {
                uint32_t a0, a1, a2, a3;
                int row = wm + mt * 16 + (lane & 15);
                int col = k0 + ((lane >> 4) << 3);
                uint32_t addr = aBase + sw128((uint32_t)(row * 128 + col * 2));
                asm volatile("ldmatrix.sync.aligned.m8n8.x4.shared.b16 {%0,%1,%2,%3}, [%4];"
                             : "=r"(a0), "=r"(a1), "=r"(a2), "=r"(a3)
                             : "r"(addr));
#pragma unroll
                for (int nt = 0; nt < 2; ++nt) {
                    asm volatile(
                        "mma.sync.aligned.m16n8k16.row.col.f32.f16.f16.f32 "
                        "{%0,%1,%2,%3}, {%4,%5,%6,%7}, {%8,%9}, {%0,%1,%2,%3};"
                        : "+f"(c[mt][nt][0]), "+f"(c[mt][nt][1]),
                          "+f"(c[mt][nt][2]), "+f"(c[mt][nt][3])
                        : "r"(a0), "r"(a1), "r"(a2), "r"(a3),
                          "r"(bfr[nt][0]), "r"(bfr[nt][1]));
                }
            }
        }

        // ---- epilogue for this half: exp + direct (i,j) store ----
        float sqj[2][2];
#pragma unroll
        for (int nt = 0; nt < 2; ++nt) {
            int cc = wn + h * 16 + nt * 8 + 2 * (lane & 3);
            sqj[nt][0] = -l2s * sSqJ[cc];
            sqj[nt][1] = -l2s * sSqJ[cc + 1];
        }

#pragma unroll
        for (int mt = 0; mt < 4; ++mt) {
            int rl = wm + mt * 16 + (lane >> 2);
            float qi0 = -l2s * sSqI[rl];
            float qi1 = -l2s * sSqI[rl + 8];
            int r = i0 + rl;
#pragma unroll
            for (int nt = 0; nt < 2; ++nt) {
                c[mt][nt][0] = exp2f(fmaf(k2, c[mt][nt][0], qi0) + sqj[nt][0]);
                c[mt][nt][1] = exp2f(fmaf(k2, c[mt][nt][1], qi0) + sqj[nt][1]);
                c[mt][nt][2] = exp2f(fmaf(k2, c[mt][nt][2], qi1) + sqj[nt][0]);
                c[mt][nt][3] = exp2f(fmaf(k2, c[mt][nt][3], qi1) + sqj[nt][1]);
                int cc = j0 + wn + h * 16 + nt * 8 + 2 * (lane & 3);
                float2 v0, v1;
                v0.x = c[mt][nt][0]; v0.y = c[mt][nt][1];
                v1.x = c[mt][nt][2]; v1.y = c[mt][nt][3];
                float* o = out + ((size_t)b * BN + r) * BN + cc;
                *(float2*)o = v0;
                *(float2*)(o + (size_t)8 * BN) = v1;
            }
        }

        // ---- mirror (j,i) store via per-warp transpose (64 rows x 16 cols -> 16 x 64) ----
        if (i0 != j0) {
            // stage: word = cl*64 + (r ^ ((cl&7)<<2)); conflict-free STS.32
#pragma unroll
            for (int mt = 0; mt < 4; ++mt)
#pragma unroll
                for (int nt = 0; nt < 2; ++nt)
#pragma unroll
                    for (int q = 0; q < 4; ++q) {
                        int r  = mt * 16 + (lane >> 2) + 8 * (q >> 1);       // 0..63
                        int cl = nt * 8 + 2 * (lane & 3) + (q & 1);          // 0..15
                        wstg[cl * 64 + (r ^ ((cl & 7) << 2))] = c[mt][nt][q];
                    }
            __syncwarp();
#pragma unroll
            for (int itx = 0; itx < 8; ++itx) {
                int cl = (lane >> 3) + 4 * (itx & 3);     // 0..15
                int rq = (lane & 7) + 8 * (itx >> 2);     // 0..15  (float4 index)
                float4 v = *(float4*)&wstg[cl * 64 + ((rq * 4) ^ ((cl & 7) << 2))];
                *(float4*)(out + ((size_t)b * BN + j0 + wn + h * 16 + cl) * BN
                               + i0 + wm + rq * 4) = v;
            }
            __syncwarp();
        }
    }
}

extern "C" void kernel_launch(void* const* d_in, const int* in_sizes, int n_in,
                              void* d_out, int out_size) {
    (void)in_sizes; (void)n_in; (void)out_size;
    const float* emb = (const float*)d_in[1];  // d_in[0] = adj_in (unused by reference)
    float* out = (float*)d_out;

    cudaFuncSetAttribute(gemm_kernel, cudaFuncAttributeMaxDynamicSharedMemorySize, SMEM_TOTAL);

    dim3 gc(BN / 64, NB);
    convert_reduce_kernel<<<gc, 256>>>(emb);
    dim3 gg(NPAIR, NB);
    gemm_kernel<<<gg, 256, SMEM_TOTAL>>>(out);
}

// round 9
// speedup vs baseline: 1.1090x; 1.1090x over previous
#include <cuda_runtime.h>
#include <cuda_fp16.h>
#include <stdint.h>

#define NB 8
#define BF 64
#define BN 2048
#define GRID_P 296            // persistent CTAs (148 SMs x 2)
#define NPAIR 136             // upper-triangle 16x16 tile pairs
#define NTASK (NPAIR * NB)    // 1088

// smem layout (dynamic):
//   [0,32K)       buf0: A(16K)|B(16K)
//   [32K,64K)     buf1: A|B
//   [64K,96K)     per-warp transpose staging, 8 x 4KB
//   [96K,+2K)     sq[2][I|J][128]
//   [+2K,+4B)     scale
//   [+2K+8,+2K+16) next-task ids, 2 slots
#define SMEM_STAGE 65536
#define SMEM_SQ    98304
#define SMEM_TOTAL (98304 + 2048 + 32)

// Scratch
__device__ __half g_emb_t[NB * BN * BF];   // transposed: [b][n][f], f contiguous (2 MB)
__device__ float  g_sqn[NB * BN];
__device__ float  g_part_sum[256];
__device__ float  g_part_sq[256];
__device__ unsigned g_task_ctr;

// ---------------- Pass 1: convert f32->f16 transposed + sqn + std partial sums ----------------
__global__ void convert_reduce_kernel(const float* __restrict__ emb) {
    int b   = blockIdx.y;
    int tid = threadIdx.x;

    // reset the gemm work-stealing counter once per launch (runs before gemm in-stream)
    if (b == 0 && blockIdx.x == 0 && tid == 0) g_task_ctr = GRID_P;

    int fq  = tid & 3;
    int nl  = tid >> 2;
    int n   = blockIdx.x * 64 + nl;

    const float* e = emb + (size_t)b * BF * BN + (size_t)(fq * 16) * BN + n;

    float s = 0.f, s2 = 0.f, sq = 0.f;
    __half2 hv[8];
#pragma unroll
    for (int i = 0; i < 16; i += 2) {
        float v0 = e[(size_t)i * BN];
        float v1 = e[(size_t)(i + 1) * BN];
        s  += v0 + v1;
        s2 += v0 * v0 + v1 * v1;
        __half h0 = __float2half(v0), h1 = __float2half(v1);
        float w0 = __half2float(h0), w1 = __half2float(h1);
        sq += w0 * w0 + w1 * w1;
        hv[i >> 1] = __halves2half2(h0, h1);
    }
    sq += __shfl_xor_sync(0xffffffffu, sq, 1);
    sq += __shfl_xor_sync(0xffffffffu, sq, 2);
    if (fq == 0) g_sqn[b * BN + n] = sq;

    uint4* dst = (uint4*)(g_emb_t + ((size_t)b * BN + n) * BF + fq * 16);
    const uint4* src = (const uint4*)hv;
    dst[0] = src[0];
    dst[1] = src[1];

    __shared__ float sh[256], sh2[256];
    sh[tid] = s; sh2[tid] = s2;
    __syncthreads();
    for (int o = 128; o > 0; o >>= 1) {
        if (tid < o) { sh[tid] += sh[tid + o]; sh2[tid] += sh2[tid + o]; }
        __syncthreads();
    }
    if (tid == 0) {
        int bi = b * 32 + blockIdx.x;
        g_part_sum[bi] = sh[0];
        g_part_sq[bi]  = sh2[0];
    }
}

// XOR swizzle for 128B rows
__device__ __forceinline__ uint32_t sw128(uint32_t off) {
    return off ^ (((off >> 7) & 7u) << 4);
}

__device__ __forceinline__ void decode_task(int task, int& b, int& i0, int& j0) {
    b = task / NPAIR;
    int t = task - b * NPAIR;
    int ti = (int)(16.5f - sqrtf(272.25f - 2.0f * (float)t));
    if (ti > 0 && 16 * ti - (ti * (ti - 1)) / 2 > t) --ti;
    while (16 * (ti + 1) - ((ti + 1) * ti) / 2 <= t) ++ti;
    int tj = ti + (t - (16 * ti - (ti * (ti - 1)) / 2));
    i0 = ti * 128;
    j0 = tj * 128;
}

__device__ __forceinline__ void issue_load(int b, int i0, int j0,
                                           uint32_t abBase, uint32_t sqBase, int tid) {
    const char* EA = (const char*)(g_emb_t + ((size_t)b * BN + i0) * BF);
    const char* EB = (const char*)(g_emb_t + ((size_t)b * BN + j0) * BF);
#pragma unroll
    for (int tt = 0; tt < 4; ++tt) {
        uint32_t off = (uint32_t)(tid + tt * 256) * 16u;
        uint32_t sw  = sw128(off);
        asm volatile("cp.async.ca.shared.global [%0], [%1], 16;" :: "r"(abBase + sw),          "l"(EA + off));
        asm volatile("cp.async.ca.shared.global [%0], [%1], 16;" :: "r"(abBase + 16384u + sw), "l"(EB + off));
    }
    if (tid < 32) {
        const char* gI = (const char*)(g_sqn + b * BN + i0) + tid * 16;
        const char* gJ = (const char*)(g_sqn + b * BN + j0) + tid * 16;
        asm volatile("cp.async.ca.shared.global [%0], [%1], 16;" :: "r"(sqBase + tid * 16u),        "l"(gI));
        asm volatile("cp.async.ca.shared.global [%0], [%1], 16;" :: "r"(sqBase + 512u + tid * 16u), "l"(gJ));
    }
}

// ---------------- Pass 2: persistent work-stealing Gram GEMM + exp + mirrored store ----------------
__global__ __launch_bounds__(256, 2) void gemm_kernel(float* __restrict__ out) {
    extern __shared__ __align__(16) char smem[];
    float* sSq     = (float*)(smem + SMEM_SQ);
    float* s_scale = (float*)(smem + SMEM_SQ + 2048);
    volatile int* s_next = (int*)(smem + SMEM_SQ + 2048 + 8);   // 2 slots

    int tid = threadIdx.x;
    uint32_t smemBase = (uint32_t)__cvta_generic_to_shared(smem);
    uint32_t sqBaseU  = smemBase + SMEM_SQ;

    int task = blockIdx.x;
    int b, i0, j0;
    decode_task(task, b, i0, j0);
    issue_load(b, i0, j0, smemBase, sqBaseU, tid);
    asm volatile("cp.async.commit_group;");

    // grab the first stolen task for iteration 0's prefetch
    if (tid == 0) s_next[0] = (int)atomicAdd(&g_task_ctr, 1u);

    // scale reduction, once per CTA (overlapped with first load)
    if (tid < 32) {
        float ps = 0.f, pq = 0.f;
#pragma unroll
        for (int i = 0; i < 8; ++i) {
            ps += g_part_sum[tid + 32 * i];
            pq += g_part_sq[tid + 32 * i];
        }
#pragma unroll
        for (int o = 16; o > 0; o >>= 1) {
            ps += __shfl_xor_sync(0xffffffffu, ps, o);
            pq += __shfl_xor_sync(0xffffffffu, pq, o);
        }
        if (tid == 0) {
            double nn  = (double)(NB * BF * BN);
            double var = ((double)pq - (double)ps * (double)ps / nn) / (nn - 1.0);
            *s_scale = (float)(1.4426950408889634 / (var * (double)BF * 2.0));
        }
    }

    asm volatile("cp.async.wait_group 0;");
    __syncthreads();

    int warp = tid >> 5, lane = tid & 31;
    int wm = (warp >> 2) * 64;
    int wn = (warp & 3) * 32;
    float l2s = *s_scale;
    float k2  = 2.f * l2s;
    float* wstg = (float*)(smem + SMEM_STAGE + warp * 4096);

    int it = 0;
    while (true) {
        int buf = it & 1;
        uint32_t aBase = smemBase + (uint32_t)buf * 32768u;
        uint32_t bBase = aBase + 16384u;

        // prefetch next (stolen) task into other buffer
        int ntask = s_next[it & 1];
        bool have_next = ntask < NTASK;
        int nb, ni, nj;
        if (have_next) {
            decode_task(ntask, nb, ni, nj);
            issue_load(nb, ni, nj, smemBase + (uint32_t)(buf ^ 1) * 32768u,
                       sqBaseU + (uint32_t)(buf ^ 1) * 1024u, tid);
        }
        asm volatile("cp.async.commit_group;");

        // ---- MMA ----
        float c[4][4][4];
#pragma unroll
        for (int mt = 0; mt < 4; ++mt)
#pragma unroll
            for (int nt = 0; nt < 4; ++nt)
#pragma unroll
                for (int q = 0; q < 4; ++q) c[mt][nt][q] = 0.f;

#pragma unroll
        for (int kk = 0; kk < 4; ++kk) {
            int k0 = kk * 16;

            uint32_t a[4][4];
#pragma unroll
            for (int mt = 0; mt < 4; ++mt) {
                int row = wm + mt * 16 + (lane & 15);
                int col = k0 + ((lane >> 4) << 3);
                uint32_t addr = aBase + sw128((uint32_t)(row * 128 + col * 2));
                asm volatile("ldmatrix.sync.aligned.m8n8.x4.shared.b16 {%0,%1,%2,%3}, [%4];"
                             : "=r"(a[mt][0]), "=r"(a[mt][1]), "=r"(a[mt][2]), "=r"(a[mt][3])
                             : "r"(addr));
            }

            uint32_t bfr[4][2];
#pragma unroll
            for (int nh = 0; nh < 2; ++nh) {
                int nrow = wn + nh * 16 + (lane & 7) + ((lane >> 4) << 3);
                int col  = k0 + (((lane >> 3) & 1) << 3);
                uint32_t addr = bBase + sw128((uint32_t)(nrow * 128 + col * 2));
                uint32_t r0, r1, r2, r3;
                asm volatile("ldmatrix.sync.aligned.m8n8.x4.shared.b16 {%0,%1,%2,%3}, [%4];"
                             : "=r"(r0), "=r"(r1), "=r"(r2), "=r"(r3)
                             : "r"(addr));
                bfr[nh * 2][0] = r0;     bfr[nh * 2][1] = r1;
                bfr[nh * 2 + 1][0] = r2; bfr[nh * 2 + 1][1] = r3;
            }

#pragma unroll
            for (int mt = 0; mt < 4; ++mt)
#pragma unroll
                for (int nt = 0; nt < 4; ++nt) {
                    asm volatile(
                        "mma.sync.aligned.m16n8k16.row.col.f32.f16.f16.f32 "
                        "{%0,%1,%2,%3}, {%4,%5,%6,%7}, {%8,%9}, {%0,%1,%2,%3};"
                        : "+f"(c[mt][nt][0]), "+f"(c[mt][nt][1]),
                          "+f"(c[mt][nt][2]), "+f"(c[mt][nt][3])
                        : "r"(a[mt][0]), "r"(a[mt][1]), "r"(a[mt][2]), "r"(a[mt][3]),
                          "r"(bfr[nt][0]), "r"(bfr[nt][1]));
                }
        }

        // ---- Epilogue: v = exp2(k2*gram - l2s*qi - l2s*qj), direct store ----
        const float* sSqI = sSq + buf * 256;
        const float* sSqJ = sSqI + 128;

        float sqj[4][2];
#pragma unroll
        for (int nt = 0; nt < 4; ++nt) {
            int cc = wn + nt * 8 + 2 * (lane & 3);
            sqj[nt][0] = -l2s * sSqJ[cc];
            sqj[nt][1] = -l2s * sSqJ[cc + 1];
        }

#pragma unroll
        for (int mt = 0; mt < 4; ++mt) {
            int rl = wm + mt * 16 + (lane >> 2);
            float qi0 = -l2s * sSqI[rl];
            float qi1 = -l2s * sSqI[rl + 8];
            int r = i0 + rl;
#pragma unroll
            for (int nt = 0; nt < 4; ++nt) {
                c[mt][nt][0] = exp2f(fmaf(k2, c[mt][nt][0], qi0) + sqj[nt][0]);
                c[mt][nt][1] = exp2f(fmaf(k2, c[mt][nt][1], qi0) + sqj[nt][1]);
                c[mt][nt][2] = exp2f(fmaf(k2, c[mt][nt][2], qi1) + sqj[nt][0]);
                c[mt][nt][3] = exp2f(fmaf(k2, c[mt][nt][3], qi1) + sqj[nt][1]);
                int cc = j0 + wn + nt * 8 + 2 * (lane & 3);
                float2 v0, v1;
                v0.x = c[mt][nt][0]; v0.y = c[mt][nt][1];
                v1.x = c[mt][nt][2]; v1.y = c[mt][nt][3];
                float* o = out + ((size_t)b * BN + r) * BN + cc;
                __stcs((float2*)o, v0);
                __stcs((float2*)(o + (size_t)8 * BN), v1);
            }
        }

        // ---- Mirror store: per-warp private transpose, no block barriers ----
        if (i0 != j0) {
#pragma unroll
            for (int h = 0; h < 2; ++h) {
#pragma unroll
                for (int mt2 = 0; mt2 < 2; ++mt2) {
                    int mt = 2 * h + mt2;
#pragma unroll
                    for (int nt = 0; nt < 4; ++nt)
#pragma unroll
                        for (int q = 0; q < 4; ++q) {
                            int rloc = mt2 * 16 + (lane >> 2) + 8 * (q >> 1);   // 0..31
                            int cc   = nt * 8 + 2 * (lane & 3) + (q & 1);        // 0..31
                            int word = cc * 32 + ((((rloc >> 2) ^ (cc & 7)) << 2) | (rloc & 3));
                            wstg[word] = c[mt][nt][q];
                        }
                }
                __syncwarp();
#pragma unroll
                for (int itx = 0; itx < 8; ++itx) {
                    int cc = itx * 4 + (lane >> 3);     // col within warp frag
                    int f  = lane & 7;
                    int fs = f ^ (cc & 7);
                    float4 v = *(float4*)&wstg[cc * 32 + 4 * fs];
                    __stcs((float4*)(out + ((size_t)b * BN + j0 + wn + cc) * BN
                                         + i0 + wm + 32 * h + 4 * f), v);
                }
                __syncwarp();
            }
        }

        if (!have_next) break;

        // steal the task after ntask; published for next iteration's slot
        if (tid == 0) s_next[(it + 1) & 1] = (int)atomicAdd(&g_task_ctr, 1u);

        asm volatile("cp.async.wait_group 0;");
        __syncthreads();
        task = ntask; b = nb; i0 = ni; j0 = nj;
        ++it;
    }
}

extern "C" void kernel_launch(void* const* d_in, const int* in_sizes, int n_in,
                              void* d_out, int out_size) {
    (void)in_sizes; (void)n_in; (void)out_size;
    const float* emb = (const float*)d_in[1];  // d_in[0] = adj_in (unused by reference)
    float* out = (float*)d_out;

    cudaFuncSetAttribute(gemm_kernel, cudaFuncAttributeMaxDynamicSharedMemorySize, SMEM_TOTAL);

    dim3 gc(BN / 64, NB);
    convert_reduce_kernel<<<gc, 256>>>(emb);
    gemm_kernel<<<GRID_P, 256, SMEM_TOTAL>>>(out);
}